// round 16
// baseline (speedup 1.0000x reference)
#include <cuda_runtime.h>
#include <cuda_bf16.h>
#include <math.h>
#include <stdint.h>

#define TT 1024
#define HH 1024
#define FF 4096
#define EE 8

// ===================== helpers ==============================================
__device__ __forceinline__ uint32_t smem_to_u32(const void* p) {
    uint32_t a;
    asm("{ .reg .u64 t; cvta.to.shared.u64 t, %1; cvt.u32.u64 %0, t; }" : "=r"(a) : "l"(p));
    return a;
}

__device__ __forceinline__ void mma_bf16(float* c, const uint32_t* a, const uint32_t* b) {
    asm volatile(
        "mma.sync.aligned.m16n8k16.row.col.f32.bf16.bf16.f32 "
        "{%0,%1,%2,%3}, {%4,%5,%6,%7}, {%8,%9}, {%0,%1,%2,%3};"
        : "+f"(c[0]), "+f"(c[1]), "+f"(c[2]), "+f"(c[3])
        : "r"(a[0]), "r"(a[1]), "r"(a[2]), "r"(a[3]), "r"(b[0]), "r"(b[1]));
}

#define CP_ASYNC16(dst32, srcp) \
    asm volatile("cp.async.cg.shared.global [%0], [%1], 16;" :: "r"(dst32), "l"(srcp))
#define CP_COMMIT() asm volatile("cp.async.commit_group;" ::: "memory")
#define CP_WAIT2()  asm volatile("cp.async.wait_group 2;" ::: "memory")
#define CP_WAIT4()  asm volatile("cp.async.wait_group 4;" ::: "memory")

// swizzled byte offset within a 32B-row tile: half = 16B chunk index (0/1)
__device__ __forceinline__ int aoff(int row, int half) {
    return row * 32 + ((half << 4) ^ ((row & 4) << 2));
}

__device__ __forceinline__ uint32_t pack_bf16(float x, float y) {
    __nv_bfloat162 p;
    p.x = __float2bfloat16(x);
    p.y = __float2bfloat16(y);
    return *reinterpret_cast<uint32_t*>(&p);
}

__device__ __forceinline__ float bf16_resid(float v) {
    return v - __bfloat162float(__float2bfloat16(v));
}

// ===================== scratch ==============================================
__device__ int   g_cnt[EE];
__device__ int   g_off[EE];
__device__ int   g_list[EE][TT];
__device__ float g_rw[TT][2];

__device__ __nv_bfloat16 g_xhi[TT * HH];
__device__ __nv_bfloat16 g_xlo[TT * HH];
__device__ __nv_bfloat16 g_wghi[(size_t)EE * FF * HH];   // [e][f][h] K-major
__device__ __nv_bfloat16 g_wglo[(size_t)EE * FF * HH];
__device__ __nv_bfloat16 g_wvhi[(size_t)EE * FF * HH];
__device__ __nv_bfloat16 g_wvlo[(size_t)EE * FF * HH];
__device__ __nv_bfloat16 g_w1hi[(size_t)EE * HH * FF];   // [e][h][f] K-major
__device__ __nv_bfloat16 g_w1lo[(size_t)EE * HH * FF];
__device__ __nv_bfloat16 g_guhi[(size_t)(2 * TT + 128) * FF];  // [grow][f] (+pad)
__device__ __nv_bfloat16 g_gulo[(size_t)(2 * TT + 128) * FF];
__device__ float g_dn[2][TT][HH];

// ===================== small kernels ========================================
__global__ void k_router(const float* __restrict__ x,
                         const float* __restrict__ wgate,
                         float* __restrict__ logits_out) {
    int t = blockIdx.x, tid = threadIdx.x;
    float acc[EE];
#pragma unroll
    for (int e = 0; e < EE; e++) acc[e] = 0.f;
    const float* xr = x + (size_t)t * HH;
    for (int h = tid; h < HH; h += 128) {
        float xv = xr[h];
        const float4* wr = (const float4*)(wgate + (size_t)h * EE);
        float4 w0 = wr[0], w1 = wr[1];
        acc[0] += xv * w0.x; acc[1] += xv * w0.y;
        acc[2] += xv * w0.z; acc[3] += xv * w0.w;
        acc[4] += xv * w1.x; acc[5] += xv * w1.y;
        acc[6] += xv * w1.z; acc[7] += xv * w1.w;
    }
    __shared__ float red[4][EE];
    int lane = tid & 31, warp = tid >> 5;
#pragma unroll
    for (int e = 0; e < EE; e++) {
        float v = acc[e];
#pragma unroll
        for (int o = 16; o > 0; o >>= 1) v += __shfl_down_sync(0xffffffffu, v, o);
        if (lane == 0) red[warp][e] = v;
    }
    __syncthreads();
    if (tid == 0) {
        float lg[EE], mx = -1e30f;
#pragma unroll
        for (int e = 0; e < EE; e++) {
            lg[e] = red[0][e] + red[1][e] + red[2][e] + red[3][e];
            logits_out[(size_t)t * EE + e] = lg[e];
            mx = fmaxf(mx, lg[e]);
        }
        float p[EE], s = 0.f;
#pragma unroll
        for (int e = 0; e < EE; e++) { p[e] = expf(lg[e] - mx); s += p[e]; }
        float inv = 1.f / s;
#pragma unroll
        for (int e = 0; e < EE; e++) p[e] *= inv;
        int i1 = 0;
#pragma unroll
        for (int e = 1; e < EE; e++) if (p[e] > p[i1]) i1 = e;
        int i2 = (i1 == 0) ? 1 : 0;
#pragma unroll
        for (int e = 0; e < EE; e++) if (e != i1 && p[e] > p[i2]) i2 = e;
        g_rw[t][0] = p[i1];
        g_rw[t][1] = p[i2];
        int q0 = atomicAdd(&g_cnt[i1], 1); g_list[i1][q0] = t * 2 + 0;
        int q1 = atomicAdd(&g_cnt[i2], 1); g_list[i2][q1] = t * 2 + 1;
    }
}

// x fp32 -> bf16 hi/lo split; block 0 thread 0 also computes expert offsets
// (router has already filled g_cnt by the time this kernel runs).
__global__ void k_prep(const float* __restrict__ x) {
    int i = blockIdx.x * blockDim.x + threadIdx.x;   // over TT*HH/4
    float4 v = ((const float4*)x)[i];
    uint2 h, l;
    h.x = pack_bf16(v.x, v.y); h.y = pack_bf16(v.z, v.w);
    l.x = pack_bf16(bf16_resid(v.x), bf16_resid(v.y));
    l.y = pack_bf16(bf16_resid(v.z), bf16_resid(v.w));
    ((uint2*)g_xhi)[i] = h;
    ((uint2*)g_xlo)[i] = l;
    if (i == 0) {
        int s = 0;
        for (int e = 0; e < EE; e++) { g_off[e] = s; s += g_cnt[e]; }
    }
}

// ===================== weight conversion (vectorized) =======================
// 64k x 64n tile per block. float4 loads -> padded smem -> 16-k transposed
// strips -> uint4 stores (32B/lane, sector-aligned). ~4 instr/element.
__global__ void __launch_bounds__(256)
k_conv_gv(const float* __restrict__ wg, const float* __restrict__ wv) {
    if (blockIdx.x == 0 && blockIdx.y == 0 && blockIdx.z == 0 && threadIdx.x < EE)
        g_cnt[threadIdx.x] = 0;
    const int K = HH, N = FF;
    int e = blockIdx.z >> 1, which = blockIdx.z & 1;
    const float* src = which ? wv : wg;
    __nv_bfloat16* hi = which ? g_wvhi : g_wghi;
    __nv_bfloat16* lo = which ? g_wvlo : g_wglo;
    int k0 = blockIdx.y * 64, n0 = blockIdx.x * 64;
    __shared__ float tile[64][68];
    int tid = threadIdx.x;
#pragma unroll
    for (int i = 0; i < 4; i++) {
        int idx = tid + 256 * i;                 // 0..1023
        int row = idx >> 4, c4 = (idx & 15) << 2;
        float4 v = *(const float4*)(src + ((size_t)e * K + k0 + row) * N + n0 + c4);
        *(float4*)&tile[row][c4] = v;
    }
    __syncthreads();
    int n = tid & 63, kq = tid >> 6;             // 64 n x 4 k-quads (16 k each)
    float vv[16];
#pragma unroll
    for (int t = 0; t < 16; t++) vv[t] = tile[kq * 16 + t][n];
    uint32_t hp[8], lp[8];
#pragma unroll
    for (int t = 0; t < 8; t++) {
        hp[t] = pack_bf16(vv[2 * t], vv[2 * t + 1]);
        lp[t] = pack_bf16(bf16_resid(vv[2 * t]), bf16_resid(vv[2 * t + 1]));
    }
    size_t o = ((size_t)e * N + n0 + n) * K + k0 + kq * 16;
    *(uint4*)&hi[o]     = make_uint4(hp[0], hp[1], hp[2], hp[3]);
    *(uint4*)&hi[o + 8] = make_uint4(hp[4], hp[5], hp[6], hp[7]);
    *(uint4*)&lo[o]     = make_uint4(lp[0], lp[1], lp[2], lp[3]);
    *(uint4*)&lo[o + 8] = make_uint4(lp[4], lp[5], lp[6], lp[7]);
}

__global__ void __launch_bounds__(256)
k_conv_w1(const float* __restrict__ w1) {
    const int K = FF, N = HH;
    int e = blockIdx.z;
    int k0 = blockIdx.y * 64, n0 = blockIdx.x * 64;
    __shared__ float tile[64][68];
    int tid = threadIdx.x;
#pragma unroll
    for (int i = 0; i < 4; i++) {
        int idx = tid + 256 * i;
        int row = idx >> 4, c4 = (idx & 15) << 2;
        float4 v = *(const float4*)(w1 + ((size_t)e * K + k0 + row) * N + n0 + c4);
        *(float4*)&tile[row][c4] = v;
    }
    __syncthreads();
    int n = tid & 63, kq = tid >> 6;
    float vv[16];
#pragma unroll
    for (int t = 0; t < 16; t++) vv[t] = tile[kq * 16 + t][n];
    uint32_t hp[8], lp[8];
#pragma unroll
    for (int t = 0; t < 8; t++) {
        hp[t] = pack_bf16(vv[2 * t], vv[2 * t + 1]);
        lp[t] = pack_bf16(bf16_resid(vv[2 * t]), bf16_resid(vv[2 * t + 1]));
    }
    size_t o = ((size_t)e * N + n0 + n) * K + k0 + kq * 16;
    *(uint4*)&g_w1hi[o]     = make_uint4(hp[0], hp[1], hp[2], hp[3]);
    *(uint4*)&g_w1hi[o + 8] = make_uint4(hp[4], hp[5], hp[6], hp[7]);
    *(uint4*)&g_w1lo[o]     = make_uint4(lp[0], lp[1], lp[2], lp[3]);
    *(uint4*)&g_w1lo[o + 8] = make_uint4(lp[4], lp[5], lp[6], lp[7]);
}

// ===================== GEMM1: gate/up (3-stage, pre-split A) ================
// Block tile M=128, N=64 (gate AND up). 8 warps = 4(m) x 2(n), warp 32x32.
// A: register-staged uint4 LDG from pre-split g_xhi/g_xlo (no converts).
// B: 3-stage cp.async. R13-proven loop ordering.
#define G1_AHI 0
#define G1_ALO 4096
#define G1_GH  8192
#define G1_GL  10240
#define G1_VH  12288
#define G1_VL  14336
#define G1_STAGE 16384
#define G1_SMEM (3 * G1_STAGE)
#define G1_NC 64            // 1024 / 16

__global__ void __launch_bounds__(256)
k_gemm1() {
    int e = blockIdx.z;
    int cnt = g_cnt[e];
    int m0 = blockIdx.y * 128;
    if (m0 >= cnt) return;
    int n0 = blockIdx.x * 64;

    extern __shared__ char smem[];
    uint32_t sb32 = smem_to_u32(smem);
    int tid = threadIdx.x;
    int lane = tid & 31, wid = tid >> 5;
    int wm = wid & 3, wn = wid >> 2;
    int qr = lane >> 2, qc = (lane & 3) << 2;

    // ---- A loader: row = tid>>1, 16B half = tid&1; pre-split bf16 ---------
    int arow = tid >> 1, aq = tid & 1;
    int ar = m0 + arow;
    int atok = (ar < cnt) ? (g_list[e][ar] >> 1) : 0;    // clamp: rows discarded
    const uint4* xh = (const uint4*)g_xhi + (size_t)atok * (HH / 8) + aq;
    const uint4* xl = (const uint4*)g_xlo + (size_t)atok * (HH / 8) + aq;
    int a_so = aoff(arow, aq);
    uint4 rh, rl;

    // ---- B loader (cp.async): grp 0 -> gate mats, 1 -> up mats ------------
    int grp = tid >> 7, rem = tid & 127, br = rem >> 1, bcb = rem & 1;
    size_t bel = ((size_t)e * FF + n0 + br) * HH + bcb * 8;
    const char* bsrc1 = (const char*)((grp ? g_wvhi : g_wghi) + bel);
    const char* bsrc2 = (const char*)((grp ? g_wvlo : g_wglo) + bel);
    uint32_t bd1 = (grp ? G1_VH : G1_GH) + aoff(br, bcb);
    uint32_t bd2 = (grp ? G1_VL : G1_GL) + aoff(br, bcb);

    auto cpB = [&](int j, int st) {
        uint32_t s = sb32 + st * G1_STAGE;
        CP_ASYNC16(s + bd1, bsrc1 + j * 32);
        CP_ASYNC16(s + bd2, bsrc2 + j * 32);
    };
    auto loadA = [&](int j) { rh = xh[j * 2]; rl = xl[j * 2]; };
    auto storeA = [&](int st) {
        char* base = smem + st * G1_STAGE;
        *(uint4*)(base + G1_AHI + a_so) = rh;
        *(uint4*)(base + G1_ALO + a_so) = rl;
    };

    float accg[2][4][4], accu[2][4][4];
#pragma unroll
    for (int i = 0; i < 2; i++)
#pragma unroll
        for (int j = 0; j < 4; j++)
#pragma unroll
            for (int q = 0; q < 4; q++) { accg[i][j][q] = 0.f; accu[i][j][q] = 0.f; }

    auto compute = [&](int st) {
        const char* base = smem + st * G1_STAGE;
        uint32_t ah[2][4], al[2][4];
#pragma unroll
        for (int i = 0; i < 2; i++) {
            int r = wm * 32 + i * 16 + qr;
            const char* pH = base + G1_AHI;
            const char* pL = base + G1_ALO;
            ah[i][0] = *(const uint32_t*)(pH + aoff(r, 0) + qc);
            ah[i][1] = *(const uint32_t*)(pH + aoff(r + 8, 0) + qc);
            ah[i][2] = *(const uint32_t*)(pH + aoff(r, 1) + qc);
            ah[i][3] = *(const uint32_t*)(pH + aoff(r + 8, 1) + qc);
            al[i][0] = *(const uint32_t*)(pL + aoff(r, 0) + qc);
            al[i][1] = *(const uint32_t*)(pL + aoff(r + 8, 0) + qc);
            al[i][2] = *(const uint32_t*)(pL + aoff(r, 1) + qc);
            al[i][3] = *(const uint32_t*)(pL + aoff(r + 8, 1) + qc);
        }
#pragma unroll
        for (int j = 0; j < 4; j++) {
            int rb = wn * 32 + j * 8 + qr;
            uint32_t bgh[2], bgl[2], bvh[2], bvl[2];
            bgh[0] = *(const uint32_t*)(base + G1_GH + aoff(rb, 0) + qc);
            bgh[1] = *(const uint32_t*)(base + G1_GH + aoff(rb, 1) + qc);
            bgl[0] = *(const uint32_t*)(base + G1_GL + aoff(rb, 0) + qc);
            bgl[1] = *(const uint32_t*)(base + G1_GL + aoff(rb, 1) + qc);
            bvh[0] = *(const uint32_t*)(base + G1_VH + aoff(rb, 0) + qc);
            bvh[1] = *(const uint32_t*)(base + G1_VH + aoff(rb, 1) + qc);
            bvl[0] = *(const uint32_t*)(base + G1_VL + aoff(rb, 0) + qc);
            bvl[1] = *(const uint32_t*)(base + G1_VL + aoff(rb, 1) + qc);
#pragma unroll
            for (int i = 0; i < 2; i++) {
                mma_bf16(accg[i][j], ah[i], bgh);
                mma_bf16(accg[i][j], al[i], bgh);
                mma_bf16(accg[i][j], ah[i], bgl);
                mma_bf16(accu[i][j], ah[i], bvh);
                mma_bf16(accu[i][j], al[i], bvh);
                mma_bf16(accu[i][j], ah[i], bvl);
            }
        }
    };

    cpB(0, 0); CP_COMMIT();
    cpB(1, 1); CP_COMMIT();
    loadA(0); storeA(0);
    loadA(1);
#pragma unroll 1
    for (int j = 0; j < G1_NC; j++) {
        __syncthreads();
        if (j + 2 < G1_NC) cpB(j + 2, (j + 2) % 3);
        CP_COMMIT();
        storeA((j + 1) % 3);
        if (j + 2 < G1_NC) loadA(j + 2);
        CP_WAIT2();
        __syncthreads();
        compute(j % 3);
    }

    int c2 = (lane & 3) << 1;
#pragma unroll
    for (int i = 0; i < 2; i++) {
        int er0 = m0 + wm * 32 + i * 16 + qr;
        int er1 = er0 + 8;
        int gr0 = g_off[e] + er0, gr1 = g_off[e] + er1;
#pragma unroll
        for (int j = 0; j < 4; j++) {
            int col = n0 + wn * 32 + j * 8 + c2;
#pragma unroll
            for (int h = 0; h < 2; h++) {
                int er = h ? er1 : er0;
                if (er >= cnt) continue;
                int grow = h ? gr1 : gr0;
                float gx = accg[i][j][h * 2 + 0], gy = accg[i][j][h * 2 + 1];
                float ux = accu[i][j][h * 2 + 0], uy = accu[i][j][h * 2 + 1];
                float g0 = 0.5f * gx * (1.f + erff(gx * 0.70710678118654752f)) * ux;
                float g1 = 0.5f * gy * (1.f + erff(gy * 0.70710678118654752f)) * uy;
                uint32_t hp = pack_bf16(g0, g1);
                uint32_t lp = pack_bf16(bf16_resid(g0), bf16_resid(g1));
                size_t bo = (size_t)grow * FF + col;
                *(uint32_t*)&g_guhi[bo] = hp;
                *(uint32_t*)&g_gulo[bo] = lp;
            }
        }
    }
}

// ===================== GEMM2: down (N=128, 512 thr, 6-stage paired) =========
#define G2_AHI 0
#define G2_ALO 4096
#define G2_BH  8192
#define G2_BL  12288
#define G2_STAGE 16384
#define G2_NSTAGE 6
#define G2_SMEM (G2_NSTAGE * G2_STAGE)
#define G2_NC 256           // 4096 / 16

__global__ void __launch_bounds__(512, 1)
k_gemm2() {
    int e = blockIdx.z;
    int cnt = g_cnt[e];
    int m0 = blockIdx.y * 128;
    if (m0 >= cnt) return;
    int n0 = blockIdx.x * 128;

    extern __shared__ char smem[];
    uint32_t sb32 = smem_to_u32(smem);
    int tid = threadIdx.x;
    int lane = tid & 31, wid = tid >> 5;
    int wm = wid & 3, wn = wid >> 2;
    int qr = lane >> 2, qc = (lane & 3) << 2;

    int grow0 = g_off[e] + m0;

    int am = tid >> 8, arem = tid & 255, ar = arem >> 1, ac = arem & 1;
    const char* asrc = (const char*)((am ? g_gulo : g_guhi) +
                       ((size_t)(grow0 + ar) * FF + ac * 8));
    uint32_t ad = (am ? G2_ALO : G2_AHI) + aoff(ar, ac);
    int bm = tid >> 8, brem = tid & 255, br = brem >> 1, bcb = brem & 1;
    const char* bsrc = (const char*)((bm ? g_w1lo : g_w1hi) +
                       (((size_t)e * HH + n0 + br) * FF + bcb * 8));
    uint32_t bd = (bm ? G2_BL : G2_BH) + aoff(br, bcb);

    auto cpAB = [&](int j, int st) {
        uint32_t s = sb32 + st * G2_STAGE;
        CP_ASYNC16(s + ad, asrc + j * 32);
        CP_ASYNC16(s + bd, bsrc + j * 32);
    };

    float acc[2][4][4];
#pragma unroll
    for (int i = 0; i < 2; i++)
#pragma unroll
        for (int j = 0; j < 4; j++)
#pragma unroll
            for (int q = 0; q < 4; q++) acc[i][j][q] = 0.f;

    auto compute = [&](int st) {
        const char* base = smem + st * G2_STAGE;
        uint32_t ah[2][4], al[2][4];
#pragma unroll
        for (int i = 0; i < 2; i++) {
            int r = wm * 32 + i * 16 + qr;
            const char* pH = base + G2_AHI;
            const char* pL = base + G2_ALO;
            ah[i][0] = *(const uint32_t*)(pH + aoff(r, 0) + qc);
            ah[i][1] = *(const uint32_t*)(pH + aoff(r + 8, 0) + qc);
            ah[i][2] = *(const uint32_t*)(pH + aoff(r, 1) + qc);
            ah[i][3] = *(const uint32_t*)(pH + aoff(r + 8, 1) + qc);
            al[i][0] = *(const uint32_t*)(pL + aoff(r, 0) + qc);
            al[i][1] = *(const uint32_t*)(pL + aoff(r + 8, 0) + qc);
            al[i][2] = *(const uint32_t*)(pL + aoff(r, 1) + qc);
            al[i][3] = *(const uint32_t*)(pL + aoff(r + 8, 1) + qc);
        }
#pragma unroll
        for (int j = 0; j < 4; j++) {
            int rb = wn * 32 + j * 8 + qr;
            uint32_t bh[2], bl[2];
            bh[0] = *(const uint32_t*)(base + G2_BH + aoff(rb, 0) + qc);
            bh[1] = *(const uint32_t*)(base + G2_BH + aoff(rb, 1) + qc);
            bl[0] = *(const uint32_t*)(base + G2_BL + aoff(rb, 0) + qc);
            bl[1] = *(const uint32_t*)(base + G2_BL + aoff(rb, 1) + qc);
#pragma unroll
            for (int i = 0; i < 2; i++) {
                mma_bf16(acc[i][j], ah[i], bh);
                mma_bf16(acc[i][j], al[i], bh);
                mma_bf16(acc[i][j], ah[i], bl);
            }
        }
    };

    cpAB(0, 0); CP_COMMIT();
    cpAB(1, 1); CP_COMMIT();
    cpAB(2, 2); CP_COMMIT();
    cpAB(3, 3); CP_COMMIT();
#pragma unroll 1
    for (int j = 0; j < G2_NC; j += 2) {
        __syncthreads();
        if (j + 4 < G2_NC) cpAB(j + 4, (j + 4) % 6);
        CP_COMMIT();
        if (j + 5 < G2_NC) cpAB(j + 5, (j + 5) % 6);
        CP_COMMIT();
        CP_WAIT4();
        __syncthreads();
        compute(j % 6);
        compute((j + 1) % 6);
    }

    int c2 = (lane & 3) << 1;
#pragma unroll
    for (int i = 0; i < 2; i++) {
        int er0 = m0 + wm * 32 + i * 16 + qr;
        int er1 = er0 + 8;
        int tok0 = 0, tok1 = 0, sl0 = 0, sl1 = 0; float w0 = 0.f, w1 = 0.f;
        if (er0 < cnt) { int ts = g_list[e][er0]; tok0 = ts >> 1; sl0 = ts & 1; w0 = g_rw[tok0][sl0]; }
        if (er1 < cnt) { int ts = g_list[e][er1]; tok1 = ts >> 1; sl1 = ts & 1; w1 = g_rw[tok1][sl1]; }
#pragma unroll
        for (int j = 0; j < 4; j++) {
            int col = n0 + wn * 32 + j * 8 + c2;
            if (er0 < cnt) {
                float* o = &g_dn[sl0][tok0][col];
                o[0] = w0 * acc[i][j][0];
                o[1] = w0 * acc[i][j][1];
            }
            if (er1 < cnt) {
                float* o = &g_dn[sl1][tok1][col];
                o[0] = w1 * acc[i][j][2];
                o[1] = w1 * acc[i][j][3];
            }
        }
    }
}

// ===================== combine ==============================================
__global__ void k_combine(float* __restrict__ out) {
    int i = blockIdx.x * blockDim.x + threadIdx.x;
    const float4* a = (const float4*)&g_dn[0][0][0];
    const float4* b = (const float4*)&g_dn[1][0][0];
    float4 u = a[i], v = b[i];
    ((float4*)out)[i] = make_float4(u.x + v.x, u.y + v.y, u.z + v.z, u.w + v.w);
}

// ===================== launch ==============================================
extern "C" void kernel_launch(void* const* d_in, const int* in_sizes, int n_in,
                              void* d_out, int out_size) {
    const float* x     = (const float*)d_in[0];
    const float* wgate = (const float*)d_in[1];
    const float* wg    = (const float*)d_in[2];
    const float* wv    = (const float*)d_in[3];
    const float* w1    = (const float*)d_in[4];
    float* out = (float*)d_out;

    cudaFuncSetAttribute(k_gemm2, cudaFuncAttributeMaxDynamicSharedMemorySize, G2_SMEM);

    // Order keeps k_gemm1 at local index 3 (lands in the ncu -s 5 window).
    k_conv_gv<<<dim3(FF / 64, HH / 64, EE * 2), 256>>>(wg, wv);      // 0 (+zero g_cnt)
    k_router<<<TT, 128>>>(x, wgate, out + (size_t)TT * HH);          // 1
    k_prep<<<(TT * HH / 4) / 256, 256>>>(x);                         // 2 (+prefix)
    k_gemm1<<<dim3(FF / 64, TT / 128, EE), 256, G1_SMEM>>>();        // 3 (ncu slot)
    k_conv_w1<<<dim3(HH / 64, FF / 64, EE), 256>>>(w1);              // 4
    k_gemm2<<<dim3(HH / 128, TT / 128, EE), 512, G2_SMEM>>>();       // 5
    k_combine<<<(TT * HH / 4) / 256, 256>>>(out);                    // 6
}

// round 17
// speedup vs baseline: 1.1074x; 1.1074x over previous
#include <cuda_runtime.h>
#include <cuda_bf16.h>
#include <math.h>
#include <stdint.h>

#define TT 1024
#define HH 1024
#define FF 4096
#define EE 8

// ===================== helpers ==============================================
__device__ __forceinline__ uint32_t smem_to_u32(const void* p) {
    uint32_t a;
    asm("{ .reg .u64 t; cvta.to.shared.u64 t, %1; cvt.u32.u64 %0, t; }" : "=r"(a) : "l"(p));
    return a;
}

__device__ __forceinline__ void mma_bf16(float* c, const uint32_t* a, const uint32_t* b) {
    asm volatile(
        "mma.sync.aligned.m16n8k16.row.col.f32.bf16.bf16.f32 "
        "{%0,%1,%2,%3}, {%4,%5,%6,%7}, {%8,%9}, {%0,%1,%2,%3};"
        : "+f"(c[0]), "+f"(c[1]), "+f"(c[2]), "+f"(c[3])
        : "r"(a[0]), "r"(a[1]), "r"(a[2]), "r"(a[3]), "r"(b[0]), "r"(b[1]));
}

#define CP_ASYNC16(dst32, srcp) \
    asm volatile("cp.async.cg.shared.global [%0], [%1], 16;" :: "r"(dst32), "l"(srcp))
#define CP_COMMIT() asm volatile("cp.async.commit_group;" ::: "memory")
#define CP_WAIT2()  asm volatile("cp.async.wait_group 2;" ::: "memory")
#define CP_WAIT4()  asm volatile("cp.async.wait_group 4;" ::: "memory")

// swizzled byte offset within a 32B-row tile: half = 16B chunk index (0/1)
__device__ __forceinline__ int aoff(int row, int half) {
    return row * 32 + ((half << 4) ^ ((row & 4) << 2));
}

__device__ __forceinline__ uint32_t pack_bf16(float x, float y) {
    __nv_bfloat162 p;
    p.x = __float2bfloat16(x);
    p.y = __float2bfloat16(y);
    return *reinterpret_cast<uint32_t*>(&p);
}

__device__ __forceinline__ float bf16_resid(float v) {
    return v - __bfloat162float(__float2bfloat16(v));
}

// ===================== scratch ==============================================
__device__ int   g_cnt[EE];
__device__ int   g_off[EE];
__device__ int   g_list[EE][TT];
__device__ float g_rw[TT][2];

__device__ __nv_bfloat16 g_wghi[(size_t)EE * FF * HH];   // [e][f][h] K-major
__device__ __nv_bfloat16 g_wglo[(size_t)EE * FF * HH];
__device__ __nv_bfloat16 g_wvhi[(size_t)EE * FF * HH];
__device__ __nv_bfloat16 g_wvlo[(size_t)EE * FF * HH];
__device__ __nv_bfloat16 g_w1hi[(size_t)EE * HH * FF];   // [e][h][f] K-major
__device__ __nv_bfloat16 g_w1lo[(size_t)EE * HH * FF];
__device__ __nv_bfloat16 g_guhi[(size_t)(2 * TT + 128) * FF];  // [grow][f] (+pad)
__device__ __nv_bfloat16 g_gulo[(size_t)(2 * TT + 128) * FF];
__device__ float g_dn[2][TT][HH];

// ===================== small kernels ========================================
__global__ void k_router(const float* __restrict__ x,
                         const float* __restrict__ wgate,
                         float* __restrict__ logits_out) {
    int t = blockIdx.x, tid = threadIdx.x;
    float acc[EE];
#pragma unroll
    for (int e = 0; e < EE; e++) acc[e] = 0.f;
    const float* xr = x + (size_t)t * HH;
    for (int h = tid; h < HH; h += 128) {
        float xv = xr[h];
        const float4* wr = (const float4*)(wgate + (size_t)h * EE);
        float4 w0 = wr[0], w1 = wr[1];
        acc[0] += xv * w0.x; acc[1] += xv * w0.y;
        acc[2] += xv * w0.z; acc[3] += xv * w0.w;
        acc[4] += xv * w1.x; acc[5] += xv * w1.y;
        acc[6] += xv * w1.z; acc[7] += xv * w1.w;
    }
    __shared__ float red[4][EE];
    int lane = tid & 31, warp = tid >> 5;
#pragma unroll
    for (int e = 0; e < EE; e++) {
        float v = acc[e];
#pragma unroll
        for (int o = 16; o > 0; o >>= 1) v += __shfl_down_sync(0xffffffffu, v, o);
        if (lane == 0) red[warp][e] = v;
    }
    __syncthreads();
    if (tid == 0) {
        float lg[EE], mx = -1e30f;
#pragma unroll
        for (int e = 0; e < EE; e++) {
            lg[e] = red[0][e] + red[1][e] + red[2][e] + red[3][e];
            logits_out[(size_t)t * EE + e] = lg[e];
            mx = fmaxf(mx, lg[e]);
        }
        float p[EE], s = 0.f;
#pragma unroll
        for (int e = 0; e < EE; e++) { p[e] = expf(lg[e] - mx); s += p[e]; }
        float inv = 1.f / s;
#pragma unroll
        for (int e = 0; e < EE; e++) p[e] *= inv;
        int i1 = 0;
#pragma unroll
        for (int e = 1; e < EE; e++) if (p[e] > p[i1]) i1 = e;
        int i2 = (i1 == 0) ? 1 : 0;
#pragma unroll
        for (int e = 0; e < EE; e++) if (e != i1 && p[e] > p[i2]) i2 = e;
        g_rw[t][0] = p[i1];
        g_rw[t][1] = p[i2];
        int q0 = atomicAdd(&g_cnt[i1], 1); g_list[i1][q0] = t * 2 + 0;
        int q1 = atomicAdd(&g_cnt[i2], 1); g_list[i2][q1] = t * 2 + 1;
    }
}

__global__ void k_prefix() {
    if (threadIdx.x == 0) {
        int s = 0;
        for (int e = 0; e < EE; e++) { g_off[e] = s; s += g_cnt[e]; }
    }
}

// ===================== weight conversion ====================================
// R15-proven 64k x 32n tile + load phase; output phase regrouped so each
// thread owns 8 consecutive k of one n row -> 2 x 16B stores per 8 elements.
// Also zeroes g_cnt (runs before k_router).
__global__ void __launch_bounds__(256)
k_conv_gv(const float* __restrict__ wg, const float* __restrict__ wv) {
    if (blockIdx.x == 0 && blockIdx.y == 0 && blockIdx.z == 0 && threadIdx.x < EE)
        g_cnt[threadIdx.x] = 0;
    const int K = HH, N = FF;
    int e = blockIdx.z >> 1, which = blockIdx.z & 1;
    const float* src = which ? wv : wg;
    __nv_bfloat16* hi = which ? g_wvhi : g_wghi;
    __nv_bfloat16* lo = which ? g_wvlo : g_wglo;
    int k0 = blockIdx.y * 64, n0 = blockIdx.x * 32;
    __shared__ float tile[64][33];
    int tid = threadIdx.x;
#pragma unroll
    for (int i = 0; i < 8; i++) {
        int idx = tid + 256 * i;
        int k = idx >> 5, n = idx & 31;
        tile[k][n] = src[((size_t)e * K + k0 + k) * N + n0 + n];
    }
    __syncthreads();
    int w = tid >> 5, l = tid & 31;
    int kb = (l & 7) * 8, nn = w * 4 + (l >> 3);
    float v[8];
#pragma unroll
    for (int t = 0; t < 8; t++) v[t] = tile[kb + t][nn];
    uint32_t hp[4], lp[4];
#pragma unroll
    for (int t = 0; t < 4; t++) {
        hp[t] = pack_bf16(v[2 * t], v[2 * t + 1]);
        lp[t] = pack_bf16(bf16_resid(v[2 * t]), bf16_resid(v[2 * t + 1]));
    }
    size_t o = ((size_t)e * N + n0 + nn) * K + k0 + kb;
    *(uint4*)&hi[o] = make_uint4(hp[0], hp[1], hp[2], hp[3]);
    *(uint4*)&lo[o] = make_uint4(lp[0], lp[1], lp[2], lp[3]);
}

__global__ void __launch_bounds__(256)
k_conv_w1(const float* __restrict__ w1) {
    const int K = FF, N = HH;
    int e = blockIdx.z;
    int k0 = blockIdx.y * 64, n0 = blockIdx.x * 32;
    __shared__ float tile[64][33];
    int tid = threadIdx.x;
#pragma unroll
    for (int i = 0; i < 8; i++) {
        int idx = tid + 256 * i;
        int k = idx >> 5, n = idx & 31;
        tile[k][n] = w1[((size_t)e * K + k0 + k) * N + n0 + n];
    }
    __syncthreads();
    int w = tid >> 5, l = tid & 31;
    int kb = (l & 7) * 8, nn = w * 4 + (l >> 3);
    float v[8];
#pragma unroll
    for (int t = 0; t < 8; t++) v[t] = tile[kb + t][nn];
    uint32_t hp[4], lp[4];
#pragma unroll
    for (int t = 0; t < 4; t++) {
        hp[t] = pack_bf16(v[2 * t], v[2 * t + 1]);
        lp[t] = pack_bf16(bf16_resid(v[2 * t]), bf16_resid(v[2 * t + 1]));
    }
    size_t o = ((size_t)e * N + n0 + nn) * K + k0 + kb;
    *(uint4*)&g_w1hi[o] = make_uint4(hp[0], hp[1], hp[2], hp[3]);
    *(uint4*)&g_w1lo[o] = make_uint4(lp[0], lp[1], lp[2], lp[3]);
}

// ===================== GEMM1: gate/up (R15-proven, 3-stage) =================
#define G1_AHI 0
#define G1_ALO 4096
#define G1_GH  8192
#define G1_GL  10240
#define G1_VH  12288
#define G1_VL  14336
#define G1_STAGE 16384
#define G1_SMEM (3 * G1_STAGE)
#define G1_NC 64            // 1024 / 16

__global__ void __launch_bounds__(256)
k_gemm1(const float* __restrict__ x) {
    int e = blockIdx.z;
    int cnt = g_cnt[e];
    int m0 = blockIdx.y * 128;
    if (m0 >= cnt) return;
    int n0 = blockIdx.x * 64;

    extern __shared__ char smem[];
    uint32_t sb32 = smem_to_u32(smem);
    int tid = threadIdx.x;
    int lane = tid & 31, wid = tid >> 5;
    int wm = wid & 3, wn = wid >> 2;
    int qr = lane >> 2, qc = (lane & 3) << 2;

    int arow = tid >> 1, aq = tid & 1;
    int ar = m0 + arow;
    int atok = (ar < cnt) ? (g_list[e][ar] >> 1) : 0;
    const float4* xs = (const float4*)x + (size_t)atok * (HH / 4) + aq * 2;
    int a_so = aoff(arow, aq);
    float4 ra0, ra1;

    int grp = tid >> 7, rem = tid & 127, br = rem >> 1, bcb = rem & 1;
    size_t bel = ((size_t)e * FF + n0 + br) * HH + bcb * 8;
    const char* bsrc1 = (const char*)((grp ? g_wvhi : g_wghi) + bel);
    const char* bsrc2 = (const char*)((grp ? g_wvlo : g_wglo) + bel);
    uint32_t bd1 = (grp ? G1_VH : G1_GH) + aoff(br, bcb);
    uint32_t bd2 = (grp ? G1_VL : G1_GL) + aoff(br, bcb);

    auto cpB = [&](int j, int st) {
        uint32_t s = sb32 + st * G1_STAGE;
        CP_ASYNC16(s + bd1, bsrc1 + j * 32);
        CP_ASYNC16(s + bd2, bsrc2 + j * 32);
    };
    auto loadA = [&](int j) { ra0 = xs[j * 4]; ra1 = xs[j * 4 + 1]; };
    auto storeA = [&](int st) {
        char* base = smem + st * G1_STAGE;
        uint4 h, l;
        h.x = pack_bf16(ra0.x, ra0.y); h.y = pack_bf16(ra0.z, ra0.w);
        h.z = pack_bf16(ra1.x, ra1.y); h.w = pack_bf16(ra1.z, ra1.w);
        l.x = pack_bf16(bf16_resid(ra0.x), bf16_resid(ra0.y));
        l.y = pack_bf16(bf16_resid(ra0.z), bf16_resid(ra0.w));
        l.z = pack_bf16(bf16_resid(ra1.x), bf16_resid(ra1.y));
        l.w = pack_bf16(bf16_resid(ra1.z), bf16_resid(ra1.w));
        *(uint4*)(base + G1_AHI + a_so) = h;
        *(uint4*)(base + G1_ALO + a_so) = l;
    };

    float accg[2][4][4], accu[2][4][4];
#pragma unroll
    for (int i = 0; i < 2; i++)
#pragma unroll
        for (int j = 0; j < 4; j++)
#pragma unroll
            for (int q = 0; q < 4; q++) { accg[i][j][q] = 0.f; accu[i][j][q] = 0.f; }

    auto compute = [&](int st) {
        const char* base = smem + st * G1_STAGE;
        uint32_t ah[2][4], al[2][4];
#pragma unroll
        for (int i = 0; i < 2; i++) {
            int r = wm * 32 + i * 16 + qr;
            const char* pH = base + G1_AHI;
            const char* pL = base + G1_ALO;
            ah[i][0] = *(const uint32_t*)(pH + aoff(r, 0) + qc);
            ah[i][1] = *(const uint32_t*)(pH + aoff(r + 8, 0) + qc);
            ah[i][2] = *(const uint32_t*)(pH + aoff(r, 1) + qc);
            ah[i][3] = *(const uint32_t*)(pH + aoff(r + 8, 1) + qc);
            al[i][0] = *(const uint32_t*)(pL + aoff(r, 0) + qc);
            al[i][1] = *(const uint32_t*)(pL + aoff(r + 8, 0) + qc);
            al[i][2] = *(const uint32_t*)(pL + aoff(r, 1) + qc);
            al[i][3] = *(const uint32_t*)(pL + aoff(r + 8, 1) + qc);
        }
#pragma unroll
        for (int j = 0; j < 4; j++) {
            int rb = wn * 32 + j * 8 + qr;
            uint32_t bgh[2], bgl[2], bvh[2], bvl[2];
            bgh[0] = *(const uint32_t*)(base + G1_GH + aoff(rb, 0) + qc);
            bgh[1] = *(const uint32_t*)(base + G1_GH + aoff(rb, 1) + qc);
            bgl[0] = *(const uint32_t*)(base + G1_GL + aoff(rb, 0) + qc);
            bgl[1] = *(const uint32_t*)(base + G1_GL + aoff(rb, 1) + qc);
            bvh[0] = *(const uint32_t*)(base + G1_VH + aoff(rb, 0) + qc);
            bvh[1] = *(const uint32_t*)(base + G1_VH + aoff(rb, 1) + qc);
            bvl[0] = *(const uint32_t*)(base + G1_VL + aoff(rb, 0) + qc);
            bvl[1] = *(const uint32_t*)(base + G1_VL + aoff(rb, 1) + qc);
#pragma unroll
            for (int i = 0; i < 2; i++) {
                mma_bf16(accg[i][j], ah[i], bgh);
                mma_bf16(accg[i][j], al[i], bgh);
                mma_bf16(accg[i][j], ah[i], bgl);
                mma_bf16(accu[i][j], ah[i], bvh);
                mma_bf16(accu[i][j], al[i], bvh);
                mma_bf16(accu[i][j], ah[i], bvl);
            }
        }
    };

    cpB(0, 0); CP_COMMIT();
    cpB(1, 1); CP_COMMIT();
    loadA(0); storeA(0);
    loadA(1);
#pragma unroll 1
    for (int j = 0; j < G1_NC; j++) {
        __syncthreads();
        if (j + 2 < G1_NC) cpB(j + 2, (j + 2) % 3);
        CP_COMMIT();
        storeA((j + 1) % 3);
        if (j + 2 < G1_NC) loadA(j + 2);
        CP_WAIT2();
        __syncthreads();
        compute(j % 3);
    }

    int c2 = (lane & 3) << 1;
#pragma unroll
    for (int i = 0; i < 2; i++) {
        int er0 = m0 + wm * 32 + i * 16 + qr;
        int er1 = er0 + 8;
        int gr0 = g_off[e] + er0, gr1 = g_off[e] + er1;
#pragma unroll
        for (int j = 0; j < 4; j++) {
            int col = n0 + wn * 32 + j * 8 + c2;
#pragma unroll
            for (int h = 0; h < 2; h++) {
                int er = h ? er1 : er0;
                if (er >= cnt) continue;
                int grow = h ? gr1 : gr0;
                float gx = accg[i][j][h * 2 + 0], gy = accg[i][j][h * 2 + 1];
                float ux = accu[i][j][h * 2 + 0], uy = accu[i][j][h * 2 + 1];
                float g0 = 0.5f * gx * (1.f + erff(gx * 0.70710678118654752f)) * ux;
                float g1 = 0.5f * gy * (1.f + erff(gy * 0.70710678118654752f)) * uy;
                uint32_t hp = pack_bf16(g0, g1);
                uint32_t lp = pack_bf16(bf16_resid(g0), bf16_resid(g1));
                size_t bo = (size_t)grow * FF + col;
                *(uint32_t*)&g_guhi[bo] = hp;
                *(uint32_t*)&g_gulo[bo] = lp;
            }
        }
    }
}

// ===================== GEMM2: down (N=128, 512 thr, 6-stage paired) =========
#define G2_AHI 0
#define G2_ALO 4096
#define G2_BH  8192
#define G2_BL  12288
#define G2_STAGE 16384
#define G2_NSTAGE 6
#define G2_SMEM (G2_NSTAGE * G2_STAGE)
#define G2_NC 256           // 4096 / 16

__global__ void __launch_bounds__(512, 1)
k_gemm2() {
    int e = blockIdx.z;
    int cnt = g_cnt[e];
    int m0 = blockIdx.y * 128;
    if (m0 >= cnt) return;
    int n0 = blockIdx.x * 128;

    extern __shared__ char smem[];
    uint32_t sb32 = smem_to_u32(smem);
    int tid = threadIdx.x;
    int lane = tid & 31, wid = tid >> 5;
    int wm = wid & 3, wn = wid >> 2;
    int qr = lane >> 2, qc = (lane & 3) << 2;

    int grow0 = g_off[e] + m0;

    int am = tid >> 8, arem = tid & 255, ar = arem >> 1, ac = arem & 1;
    const char* asrc = (const char*)((am ? g_gulo : g_guhi) +
                       ((size_t)(grow0 + ar) * FF + ac * 8));
    uint32_t ad = (am ? G2_ALO : G2_AHI) + aoff(ar, ac);
    int bm = tid >> 8, brem = tid & 255, br = brem >> 1, bcb = brem & 1;
    const char* bsrc = (const char*)((bm ? g_w1lo : g_w1hi) +
                       (((size_t)e * HH + n0 + br) * FF + bcb * 8));
    uint32_t bd = (bm ? G2_BL : G2_BH) + aoff(br, bcb);

    auto cpAB = [&](int j, int st) {
        uint32_t s = sb32 + st * G2_STAGE;
        CP_ASYNC16(s + ad, asrc + j * 32);
        CP_ASYNC16(s + bd, bsrc + j * 32);
    };

    float acc[2][4][4];
#pragma unroll
    for (int i = 0; i < 2; i++)
#pragma unroll
        for (int j = 0; j < 4; j++)
#pragma unroll
            for (int q = 0; q < 4; q++) acc[i][j][q] = 0.f;

    auto compute = [&](int st) {
        const char* base = smem + st * G2_STAGE;
        uint32_t ah[2][4], al[2][4];
#pragma unroll
        for (int i = 0; i < 2; i++) {
            int r = wm * 32 + i * 16 + qr;
            const char* pH = base + G2_AHI;
            const char* pL = base + G2_ALO;
            ah[i][0] = *(const uint32_t*)(pH + aoff(r, 0) + qc);
            ah[i][1] = *(const uint32_t*)(pH + aoff(r + 8, 0) + qc);
            ah[i][2] = *(const uint32_t*)(pH + aoff(r, 1) + qc);
            ah[i][3] = *(const uint32_t*)(pH + aoff(r + 8, 1) + qc);
            al[i][0] = *(const uint32_t*)(pL + aoff(r, 0) + qc);
            al[i][1] = *(const uint32_t*)(pL + aoff(r + 8, 0) + qc);
            al[i][2] = *(const uint32_t*)(pL + aoff(r, 1) + qc);
            al[i][3] = *(const uint32_t*)(pL + aoff(r + 8, 1) + qc);
        }
#pragma unroll
        for (int j = 0; j < 4; j++) {
            int rb = wn * 32 + j * 8 + qr;
            uint32_t bh[2], bl[2];
            bh[0] = *(const uint32_t*)(base + G2_BH + aoff(rb, 0) + qc);
            bh[1] = *(const uint32_t*)(base + G2_BH + aoff(rb, 1) + qc);
            bl[0] = *(const uint32_t*)(base + G2_BL + aoff(rb, 0) + qc);
            bl[1] = *(const uint32_t*)(base + G2_BL + aoff(rb, 1) + qc);
#pragma unroll
            for (int i = 0; i < 2; i++) {
                mma_bf16(acc[i][j], ah[i], bh);
                mma_bf16(acc[i][j], al[i], bh);
                mma_bf16(acc[i][j], ah[i], bl);
            }
        }
    };

    cpAB(0, 0); CP_COMMIT();
    cpAB(1, 1); CP_COMMIT();
    cpAB(2, 2); CP_COMMIT();
    cpAB(3, 3); CP_COMMIT();
#pragma unroll 1
    for (int j = 0; j < G2_NC; j += 2) {
        __syncthreads();
        if (j + 4 < G2_NC) cpAB(j + 4, (j + 4) % 6);
        CP_COMMIT();
        if (j + 5 < G2_NC) cpAB(j + 5, (j + 5) % 6);
        CP_COMMIT();
        CP_WAIT4();
        __syncthreads();
        compute(j % 6);
        compute((j + 1) % 6);
    }

    int c2 = (lane & 3) << 1;
#pragma unroll
    for (int i = 0; i < 2; i++) {
        int er0 = m0 + wm * 32 + i * 16 + qr;
        int er1 = er0 + 8;
        int tok0 = 0, tok1 = 0, sl0 = 0, sl1 = 0; float w0 = 0.f, w1 = 0.f;
        if (er0 < cnt) { int ts = g_list[e][er0]; tok0 = ts >> 1; sl0 = ts & 1; w0 = g_rw[tok0][sl0]; }
        if (er1 < cnt) { int ts = g_list[e][er1]; tok1 = ts >> 1; sl1 = ts & 1; w1 = g_rw[tok1][sl1]; }
#pragma unroll
        for (int j = 0; j < 4; j++) {
            int col = n0 + wn * 32 + j * 8 + c2;
            if (er0 < cnt) {
                float* o = &g_dn[sl0][tok0][col];
                o[0] = w0 * acc[i][j][0];
                o[1] = w0 * acc[i][j][1];
            }
            if (er1 < cnt) {
                float* o = &g_dn[sl1][tok1][col];
                o[0] = w1 * acc[i][j][2];
                o[1] = w1 * acc[i][j][3];
            }
        }
    }
}

// ===================== combine ==============================================
__global__ void k_combine(float* __restrict__ out) {
    int i = blockIdx.x * blockDim.x + threadIdx.x;
    const float4* a = (const float4*)&g_dn[0][0][0];
    const float4* b = (const float4*)&g_dn[1][0][0];
    float4 u = a[i], v = b[i];
    ((float4*)out)[i] = make_float4(u.x + v.x, u.y + v.y, u.z + v.z, u.w + v.w);
}

// ===================== launch ==============================================
extern "C" void kernel_launch(void* const* d_in, const int* in_sizes, int n_in,
                              void* d_out, int out_size) {
    const float* x     = (const float*)d_in[0];
    const float* wgate = (const float*)d_in[1];
    const float* wg    = (const float*)d_in[2];
    const float* wv    = (const float*)d_in[3];
    const float* w1    = (const float*)d_in[4];
    float* out = (float*)d_out;

    cudaFuncSetAttribute(k_gemm2, cudaFuncAttributeMaxDynamicSharedMemorySize, G2_SMEM);

    // Order keeps k_gemm1 at local index 3 (lands in the ncu -s 5 window).
    k_conv_gv<<<dim3(FF / 32, HH / 64, EE * 2), 256>>>(wg, wv);      // 0 (+zero g_cnt)
    k_router<<<TT, 128>>>(x, wgate, out + (size_t)TT * HH);          // 1
    k_prefix<<<1, 32>>>();                                           // 2
    k_gemm1<<<dim3(FF / 64, TT / 128, EE), 256, G1_SMEM>>>(x);       // 3 (ncu slot)
    k_conv_w1<<<dim3(HH / 32, FF / 64, EE), 256>>>(w1);              // 4
    k_gemm2<<<dim3(HH / 128, TT / 128, EE), 512, G2_SMEM>>>();       // 5
    k_combine<<<(TT * HH / 4) / 256, 256>>>(out);                    // 6
}